// round 6
// baseline (speedup 1.0000x reference)
#include <cuda_runtime.h>
#include <cstdint>
#include <cstddef>

#define BB 32
#define SQ 2048
#define SK 2048
#define DD 64
#define QB 128           // q rows per CTA
#define KB 128           // k cols per tile
#define NT 256
#define NTILES (SK/KB)

#define KSTR 68          // K raw tile row stride (floats) -> conflict-free
#define VSTR 72          // V raw tile row stride (floats) -> conflict-free for PV frags
#define PSTR 132         // P tile row stride

// float-index offsets in dynamic smem
#define OFF_K   0                        // 2 buffers x 128*KSTR
#define OFF_V   (2*128*KSTR)             // 17408 : 2 buffers x 128*VSTR
#define OFF_P   (OFF_V + 2*128*VSTR)     // 35840 : 128*PSTR
#define SMEM_FLOATS (OFF_P + 128*PSTR)   // 52736
#define SMEM_BYTES  (SMEM_FLOATS*4)      // 210944 B

#define KBUF_FLOATS (128*KSTR)
#define VBUF_FLOATS (128*VSTR)

__device__ float g_inv[BB * SQ];      // per-row 1/rowsum scratch

static __device__ __forceinline__ uint32_t f2tf(float x) {
    uint32_t r; asm("cvt.rna.tf32.f32 %0, %1;" : "=r"(r) : "f"(x)); return r;
}
static __device__ __forceinline__ void mma8(float& d0, float& d1, float& d2, float& d3,
                                            uint32_t a0, uint32_t a1, uint32_t a2, uint32_t a3,
                                            uint32_t b0, uint32_t b1) {
    asm volatile("mma.sync.aligned.m16n8k8.row.col.f32.tf32.tf32.f32 "
                 "{%0,%1,%2,%3}, {%4,%5,%6,%7}, {%8,%9}, {%0,%1,%2,%3};"
                 : "+f"(d0), "+f"(d1), "+f"(d2), "+f"(d3)
                 : "r"(a0), "r"(a1), "r"(a2), "r"(a3), "r"(b0), "r"(b1));
}
static __device__ __forceinline__ void cpasync16(uint32_t dst, const void* src) {
    asm volatile("cp.async.cg.shared.global [%0], [%1], 16;" :: "r"(dst), "l"(src));
}

__global__ void __launch_bounds__(NT, 1)
attn_pass1(const float* __restrict__ Qg, const float* __restrict__ Kg,
           const float* __restrict__ Vg, const int* __restrict__ Mg,
           float* __restrict__ attn, float* __restrict__ Og)
{
    extern __shared__ float sm[];
    const uint32_t smb = (uint32_t)__cvta_generic_to_shared(sm);

    const int tid  = threadIdx.x;
    const int w    = tid >> 5;
    const int lane = tid & 31;
    const int q    = lane & 3;        // col pair within fragment
    const int g    = lane >> 2;       // row within fragment
    const int b    = blockIdx.y;
    const int qbase = blockIdx.x * QB;

    const int r0 = w * 16 + g;
    const size_t grow0 = (size_t)b * SQ + qbase + r0;
    const size_t grow1 = grow0 + 8;

    // ---- stage Q (scaled, hi/lo tf32 split) via the two K buffers, lift frags ----
    {
        uint32_t* QH = (uint32_t*)(sm + OFF_K);
        uint32_t* QL = (uint32_t*)(sm + OFF_K + KBUF_FLOATS);
        const float4* Qv = (const float4*)(Qg + ((size_t)b * SQ + qbase) * DD);
        for (int v = tid; v < QB * DD / 4; v += NT) {
            int row = v >> 4, c = (v & 15) * 4;
            float4 x = Qv[v];
            x.x *= 0.125f; x.y *= 0.125f; x.z *= 0.125f; x.w *= 0.125f;
            uint4 hi, lo;
            hi.x = f2tf(x.x); lo.x = f2tf(x.x - __uint_as_float(hi.x));
            hi.y = f2tf(x.y); lo.y = f2tf(x.y - __uint_as_float(hi.y));
            hi.z = f2tf(x.z); lo.z = f2tf(x.z - __uint_as_float(hi.z));
            hi.w = f2tf(x.w); lo.w = f2tf(x.w - __uint_as_float(hi.w));
            *(uint4*)&QH[row * KSTR + c] = hi;
            *(uint4*)&QL[row * KSTR + c] = lo;
        }
        __syncthreads();

        // fragment lift happens below (needs QH/QL still valid)
    }

    uint32_t qhi[8][4], qlo[8][4];
    {
        uint32_t* QH = (uint32_t*)(sm + OFF_K);
        uint32_t* QL = (uint32_t*)(sm + OFF_K + KBUF_FLOATS);
        #pragma unroll
        for (int s = 0; s < 8; s++) {
            const int c0 = s * 8 + q;
            qhi[s][0] = QH[r0 * KSTR + c0];
            qhi[s][1] = QH[(r0 + 8) * KSTR + c0];
            qhi[s][2] = QH[r0 * KSTR + c0 + 4];
            qhi[s][3] = QH[(r0 + 8) * KSTR + c0 + 4];
            qlo[s][0] = QL[r0 * KSTR + c0];
            qlo[s][1] = QL[(r0 + 8) * KSTR + c0];
            qlo[s][2] = QL[r0 * KSTR + c0 + 4];
            qlo[s][3] = QL[(r0 + 8) * KSTR + c0 + 4];
        }
    }
    __syncthreads();   // Q staging done; K buffers free for the pipeline

    uint32_t* Pu = (uint32_t*)(sm + OFF_P);

    const float* Kbase = Kg + (size_t)b * SK * DD;
    const float* Vbase = Vg + (size_t)b * SK * DD;

    // ---- cp.async tile loader: raw fp32 K and V into buffer `buf` ----
    auto issue_tile = [&](int t, int buf) {
        const float4* Kv = (const float4*)(Kbase + (size_t)t * KB * DD);
        const float4* Vv = (const float4*)(Vbase + (size_t)t * KB * DD);
        const uint32_t kd = smb + (OFF_K + buf * KBUF_FLOATS) * 4;
        const uint32_t vd = smb + (OFF_V + buf * VBUF_FLOATS) * 4;
        #pragma unroll
        for (int it = 0; it < (KB * DD / 4) / NT; it++) {
            int v = tid + it * NT;
            int row = v >> 4, c = (v & 15) * 4;
            cpasync16(kd + (row * KSTR + c) * 4, Kv + v);
            cpasync16(vd + (row * VSTR + c) * 4, Vv + v);
        }
        asm volatile("cp.async.commit_group;" ::: "memory");
    };

    issue_tile(0, 0);

    float oacc[8][4];
    #pragma unroll
    for (int i = 0; i < 8; i++)
        oacc[i][0] = oacc[i][1] = oacc[i][2] = oacc[i][3] = 0.f;
    float lsum0 = 0.f, lsum1 = 0.f;

    // rolling mask prefetch (block 0 of tile 0)
    int2 m0 = *(const int2*)(Mg + grow0 * SK + 2 * q);
    int2 m1 = *(const int2*)(Mg + grow1 * SK + 2 * q);

    for (int t = 0; t < NTILES; t++) {
        if (t + 1 < NTILES) {
            issue_tile(t + 1, (t + 1) & 1);
            asm volatile("cp.async.wait_group 1;" ::: "memory");
        } else {
            asm volatile("cp.async.wait_group 0;" ::: "memory");
        }
        __syncthreads();   // tile t visible to all warps

        const float* Kraw = sm + OFF_K + (t & 1) * KBUF_FLOATS;
        const float* Vraw = sm + OFF_V + (t & 1) * VBUF_FLOATS;

        // ---- QK (3xTF32, inline hi/lo split of K) + fused epilogue ----
        #pragma unroll 1
        for (int nb = 0; nb < 16; nb++) {
            // prefetch next block's mask (rolls into next tile at nb==15)
            int2 m0n, m1n;
            if (t < NTILES - 1 || nb < 15) {
                const int ncol = t * KB + (nb + 1) * 8 + 2 * q;
                m0n = *(const int2*)(Mg + grow0 * SK + ncol);
                m1n = *(const int2*)(Mg + grow1 * SK + ncol);
            }

            float a0 = 0.f, a1 = 0.f, a2 = 0.f, a3 = 0.f;
            float c0 = 0.f, c1 = 0.f, c2 = 0.f, c3 = 0.f;
            const int nrow = nb * 8 + g;
            #pragma unroll
            for (int s = 0; s < 8; s++) {
                const int cc = s * 8 + q;
                const float kr0 = Kraw[nrow * KSTR + cc];
                const float kr1 = Kraw[nrow * KSTR + cc + 4];
                const uint32_t bh0 = f2tf(kr0);
                const uint32_t bh1 = f2tf(kr1);
                const uint32_t bl0 = f2tf(kr0 - __uint_as_float(bh0));
                const uint32_t bl1 = f2tf(kr1 - __uint_as_float(bh1));
                mma8(a0, a1, a2, a3, qhi[s][0], qhi[s][1], qhi[s][2], qhi[s][3], bh0, bh1);
                mma8(c0, c1, c2, c3, qlo[s][0], qlo[s][1], qlo[s][2], qlo[s][3], bh0, bh1);
                mma8(c0, c1, c2, c3, qhi[s][0], qhi[s][1], qhi[s][2], qhi[s][3], bl0, bl1);
            }
            const float s00 = a0 + c0, s01 = a1 + c1, s10 = a2 + c2, s11 = a3 + c3;

            const int col = t * KB + nb * 8 + 2 * q;
            float e00 = m0.x ? __expf(s00) : 0.f;
            float e01 = m0.y ? __expf(s01) : 0.f;
            float e10 = m1.x ? __expf(s10) : 0.f;
            float e11 = m1.y ? __expf(s11) : 0.f;
            float2 w0; w0.x = e00; w0.y = e01;
            float2 w1; w1.x = e10; w1.y = e11;
            *(float2*)(attn + grow0 * SK + col) = w0;
            *(float2*)(attn + grow1 * SK + col) = w1;
            lsum0 += e00 + e01;
            lsum1 += e10 + e11;

            uint2 p0; p0.x = f2tf(e00); p0.y = f2tf(e01);
            uint2 p1; p1.x = f2tf(e10); p1.y = f2tf(e11);
            *(uint2*)&Pu[r0 * PSTR + nb * 8 + 2 * q] = p0;        // warp-private strip
            *(uint2*)&Pu[(r0 + 8) * PSTR + nb * 8 + 2 * q] = p1;

            m0 = m0n; m1 = m1n;
        }

        // ---- O += P @ V (k=128: 16 steps; n=64: 8 blocks), inline tf32 cvt of V ----
        #pragma unroll 1
        for (int s2 = 0; s2 < 16; s2++) {
            const int cc = s2 * 8 + q;
            const uint32_t pa0 = Pu[r0 * PSTR + cc];
            const uint32_t pa1 = Pu[(r0 + 8) * PSTR + cc];
            const uint32_t pa2 = Pu[r0 * PSTR + cc + 4];
            const uint32_t pa3 = Pu[(r0 + 8) * PSTR + cc + 4];
            const int vr0 = s2 * 8 + q;
            #pragma unroll
            for (int nb2 = 0; nb2 < 8; nb2++) {
                const uint32_t vb0 = f2tf(Vraw[vr0 * VSTR + nb2 * 8 + g]);
                const uint32_t vb1 = f2tf(Vraw[(vr0 + 4) * VSTR + nb2 * 8 + g]);
                mma8(oacc[nb2][0], oacc[nb2][1], oacc[nb2][2], oacc[nb2][3],
                     pa0, pa1, pa2, pa3, vb0, vb1);
            }
        }
        __syncthreads();   // all warps done with buf[t&1] before it is refilled
    }

    // ---- finalize: row sums via butterfly within 4-lane groups ----
    #pragma unroll
    for (int off = 1; off <= 2; off <<= 1) {
        lsum0 += __shfl_xor_sync(0xffffffffu, lsum0, off);
        lsum1 += __shfl_xor_sync(0xffffffffu, lsum1, off);
    }
    const float inv0 = 1.0f / lsum0;
    const float inv1 = 1.0f / lsum1;
    if (q == 0) {
        g_inv[grow0] = inv0;
        g_inv[grow1] = inv1;
    }

    #pragma unroll
    for (int nb2 = 0; nb2 < 8; nb2++) {
        float2 o0; o0.x = oacc[nb2][0] * inv0; o0.y = oacc[nb2][1] * inv0;
        float2 o1; o1.x = oacc[nb2][2] * inv1; o1.y = oacc[nb2][3] * inv1;
        *(float2*)(Og + grow0 * DD + nb2 * 8 + 2 * q) = o0;
        *(float2*)(Og + grow1 * DD + nb2 * 8 + 2 * q) = o1;
    }
}

// ---- pass 2: normalize attn rows by 1/rowsum ----
__global__ void __launch_bounds__(256)
attn_norm(float* __restrict__ attn)
{
    const int row = blockIdx.x;
    const float inv = g_inv[row];
    float4* p = (float4*)(attn + (size_t)row * SK);
    const int i = threadIdx.x;
    #pragma unroll
    for (int k = 0; k < 2; k++) {
        float4 x = p[i + k * 256];
        x.x *= inv; x.y *= inv; x.z *= inv; x.w *= inv;
        p[i + k * 256] = x;
    }
}

extern "C" void kernel_launch(void* const* d_in, const int* in_sizes, int n_in,
                              void* d_out, int out_size)
{
    const float* Q    = (const float*)d_in[0];
    const float* K    = (const float*)d_in[1];
    const float* V    = (const float*)d_in[2];
    const int*   mask = (const int*)d_in[3];

    float* attn = (float*)d_out;                   // [B, SQ, SK]
    float* outp = attn + (size_t)BB * SQ * SK;     // [B, SQ, D]

    cudaFuncSetAttribute(attn_pass1,
                         cudaFuncAttributeMaxDynamicSharedMemorySize, SMEM_BYTES);

    dim3 grid(SQ / QB, BB);
    attn_pass1<<<grid, NT, SMEM_BYTES>>>(Q, K, V, mask, attn, outp);
    attn_norm<<<BB * SQ, 256>>>(attn);
}

// round 7
// speedup vs baseline: 1.0844x; 1.0844x over previous
#include <cuda_runtime.h>
#include <cstdint>
#include <cstddef>

#define BB 32
#define SQ 2048
#define SK 2048
#define DD 64
#define QB 128           // q rows per CTA
#define KB 128           // k cols per tile
#define NT 256
#define NTILES (SK/KB)

#define KSTR 68          // K hi/lo tile row stride (floats)
#define VSTR 72          // V tile row stride
#define PSTR 132         // P tile row stride

// float-index offsets in dynamic smem
#define OFF_KHI 0
#define OFF_KLO (128*KSTR)            // 8704
#define OFF_VT  (OFF_KLO + 128*KSTR)  // 17408
#define OFF_P   (OFF_VT + 128*VSTR)   // 26624
#define SMEM_FLOATS (OFF_P + 128*PSTR)
#define SMEM_BYTES  (SMEM_FLOATS*4)   // 174080 B

__device__ float g_inv[BB * SQ];      // per-row 1/rowsum scratch

static __device__ __forceinline__ uint32_t f2tf(float x) {
    uint32_t r; asm("cvt.rna.tf32.f32 %0, %1;" : "=r"(r) : "f"(x)); return r;
}
static __device__ __forceinline__ void mma8(float& d0, float& d1, float& d2, float& d3,
                                            uint32_t a0, uint32_t a1, uint32_t a2, uint32_t a3,
                                            uint32_t b0, uint32_t b1) {
    asm volatile("mma.sync.aligned.m16n8k8.row.col.f32.tf32.tf32.f32 "
                 "{%0,%1,%2,%3}, {%4,%5,%6,%7}, {%8,%9}, {%0,%1,%2,%3};"
                 : "+f"(d0), "+f"(d1), "+f"(d2), "+f"(d3)
                 : "r"(a0), "r"(a1), "r"(a2), "r"(a3), "r"(b0), "r"(b1));
}

__global__ void __launch_bounds__(NT, 1)
attn_pass1(const float* __restrict__ Qg, const float* __restrict__ Kg,
           const float* __restrict__ Vg, const int* __restrict__ Mg,
           float* __restrict__ attn, float* __restrict__ Og)
{
    extern __shared__ float sm[];
    uint32_t* KHu = (uint32_t*)(sm + OFF_KHI);
    uint32_t* KLu = (uint32_t*)(sm + OFF_KLO);
    uint32_t* VTu = (uint32_t*)(sm + OFF_VT);
    uint32_t* Pu  = (uint32_t*)(sm + OFF_P);

    const int tid  = threadIdx.x;
    const int w    = tid >> 5;
    const int lane = tid & 31;
    const int q    = lane & 3;        // thread-in-group (col within fragment)
    const int g    = lane >> 2;       // group id (row within fragment)
    const int b    = blockIdx.y;
    const int qbase = blockIdx.x * QB;

    const int r0 = w * 16 + g;        // local q row (and r0+8)
    const size_t grow0 = (size_t)b * SQ + qbase + r0;
    const size_t grow1 = grow0 + 8;

    // ---- stage Q (scaled 0.125, hi/lo tf32 split) into KHI/KLO, then lift frags to regs ----
    {
        const float4* Qv = (const float4*)(Qg + ((size_t)b * SQ + qbase) * DD);
        for (int v = tid; v < QB * DD / 4; v += NT) {
            int row = v >> 4, c = (v & 15) * 4;
            float4 x = Qv[v];
            x.x *= 0.125f; x.y *= 0.125f; x.z *= 0.125f; x.w *= 0.125f;
            uint4 hi, lo;
            hi.x = f2tf(x.x); lo.x = f2tf(x.x - __uint_as_float(hi.x));
            hi.y = f2tf(x.y); lo.y = f2tf(x.y - __uint_as_float(hi.y));
            hi.z = f2tf(x.z); lo.z = f2tf(x.z - __uint_as_float(hi.z));
            hi.w = f2tf(x.w); lo.w = f2tf(x.w - __uint_as_float(hi.w));
            *(uint4*)&KHu[row * KSTR + c] = hi;
            *(uint4*)&KLu[row * KSTR + c] = lo;
        }
    }
    __syncthreads();

    uint32_t qhi[8][4], qlo[8][4];
    #pragma unroll
    for (int s = 0; s < 8; s++) {
        const int c0 = s * 8 + q;
        qhi[s][0] = KHu[r0 * KSTR + c0];
        qhi[s][1] = KHu[(r0 + 8) * KSTR + c0];
        qhi[s][2] = KHu[r0 * KSTR + c0 + 4];
        qhi[s][3] = KHu[(r0 + 8) * KSTR + c0 + 4];
        qlo[s][0] = KLu[r0 * KSTR + c0];
        qlo[s][1] = KLu[(r0 + 8) * KSTR + c0];
        qlo[s][2] = KLu[r0 * KSTR + c0 + 4];
        qlo[s][3] = KLu[(r0 + 8) * KSTR + c0 + 4];
    }
    __syncthreads();

    float oacc[8][4];
    #pragma unroll
    for (int i = 0; i < 8; i++)
        oacc[i][0] = oacc[i][1] = oacc[i][2] = oacc[i][3] = 0.f;
    float lsum0 = 0.f, lsum1 = 0.f;

    // rolling mask prefetch (block 0 of tile 0)
    int2 m0 = *(const int2*)(Mg + grow0 * SK + 2 * q);
    int2 m1 = *(const int2*)(Mg + grow1 * SK + 2 * q);

    for (int t = 0; t < NTILES; t++) {
        // ---- load K tile (hi/lo split) + V tile (tf32) ----
        const float4* Kv = (const float4*)(Kg + ((size_t)b * SK + (size_t)t * KB) * DD);
        const float4* Vv = (const float4*)(Vg + ((size_t)b * SK + (size_t)t * KB) * DD);
        for (int v = tid; v < KB * DD / 4; v += NT) {
            int row = v >> 4, c = (v & 15) * 4;
            float4 x = Kv[v];
            uint4 hi, lo;
            hi.x = f2tf(x.x); lo.x = f2tf(x.x - __uint_as_float(hi.x));
            hi.y = f2tf(x.y); lo.y = f2tf(x.y - __uint_as_float(hi.y));
            hi.z = f2tf(x.z); lo.z = f2tf(x.z - __uint_as_float(hi.z));
            hi.w = f2tf(x.w); lo.w = f2tf(x.w - __uint_as_float(hi.w));
            *(uint4*)&KHu[row * KSTR + c] = hi;
            *(uint4*)&KLu[row * KSTR + c] = lo;
            float4 y = Vv[v];
            uint4 vt;
            vt.x = f2tf(y.x); vt.y = f2tf(y.y); vt.z = f2tf(y.z); vt.w = f2tf(y.w);
            *(uint4*)&VTu[row * VSTR + c] = vt;
        }
        __syncthreads();

        // ---- QK (3xTF32, 4 independent accumulator chains) + fused epilogue ----
        #pragma unroll 1
        for (int nb = 0; nb < 16; nb++) {
            // prefetch next block's mask (rolls into next tile at nb==15)
            int2 m0n = {0, 0}, m1n = {0, 0};
            if (t < NTILES - 1 || nb < 15) {
                const int ncol = t * KB + (nb + 1) * 8 + 2 * q;
                m0n = *(const int2*)(Mg + grow0 * SK + ncol);
                m1n = *(const int2*)(Mg + grow1 * SK + ncol);
            }

            float a0 = 0.f, a1 = 0.f, a2 = 0.f, a3 = 0.f;     // hi*hi, even k-steps
            float b0 = 0.f, b1 = 0.f, b2 = 0.f, b3 = 0.f;     // hi*hi, odd k-steps
            float c0 = 0.f, c1 = 0.f, c2 = 0.f, c3 = 0.f;     // lo*hi
            float d0 = 0.f, d1 = 0.f, d2 = 0.f, d3 = 0.f;     // hi*lo
            const int nrow = nb * 8 + g;
            #pragma unroll
            for (int s = 0; s < 8; s++) {
                const int cc = s * 8 + q;
                const uint32_t bh0 = KHu[nrow * KSTR + cc];
                const uint32_t bh1 = KHu[nrow * KSTR + cc + 4];
                const uint32_t bl0 = KLu[nrow * KSTR + cc];
                const uint32_t bl1 = KLu[nrow * KSTR + cc + 4];
                if (s & 1)
                    mma8(b0, b1, b2, b3, qhi[s][0], qhi[s][1], qhi[s][2], qhi[s][3], bh0, bh1);
                else
                    mma8(a0, a1, a2, a3, qhi[s][0], qhi[s][1], qhi[s][2], qhi[s][3], bh0, bh1);
                mma8(c0, c1, c2, c3, qlo[s][0], qlo[s][1], qlo[s][2], qlo[s][3], bh0, bh1);
                mma8(d0, d1, d2, d3, qhi[s][0], qhi[s][1], qhi[s][2], qhi[s][3], bl0, bl1);
            }
            const float s00 = (a0 + b0) + (c0 + d0);
            const float s01 = (a1 + b1) + (c1 + d1);
            const float s10 = (a2 + b2) + (c2 + d2);
            const float s11 = (a3 + b3) + (c3 + d3);

            const int col = t * KB + nb * 8 + 2 * q;
            float e00 = m0.x ? __expf(s00) : 0.f;
            float e01 = m0.y ? __expf(s01) : 0.f;
            float e10 = m1.x ? __expf(s10) : 0.f;
            float e11 = m1.y ? __expf(s11) : 0.f;
            float2 w0; w0.x = e00; w0.y = e01;
            float2 w1; w1.x = e10; w1.y = e11;
            *(float2*)(attn + grow0 * SK + col) = w0;
            *(float2*)(attn + grow1 * SK + col) = w1;
            lsum0 += e00 + e01;
            lsum1 += e10 + e11;

            uint2 p0; p0.x = f2tf(e00); p0.y = f2tf(e01);
            uint2 p1; p1.x = f2tf(e10); p1.y = f2tf(e11);
            *(uint2*)&Pu[r0 * PSTR + nb * 8 + 2 * q] = p0;        // warp-private strip
            *(uint2*)&Pu[(r0 + 8) * PSTR + nb * 8 + 2 * q] = p1;

            m0 = m0n; m1 = m1n;
        }

        // ---- O += P @ V (k=128: 16 steps; n=64: 8 independent chains) ----
        #pragma unroll 1
        for (int s2 = 0; s2 < 16; s2++) {
            const int cc = s2 * 8 + q;
            const uint32_t pa0 = Pu[r0 * PSTR + cc];
            const uint32_t pa1 = Pu[(r0 + 8) * PSTR + cc];
            const uint32_t pa2 = Pu[r0 * PSTR + cc + 4];
            const uint32_t pa3 = Pu[(r0 + 8) * PSTR + cc + 4];
            const int vr0 = s2 * 8 + q;
            #pragma unroll
            for (int nb2 = 0; nb2 < 8; nb2++) {
                const uint32_t vb0 = VTu[vr0 * VSTR + nb2 * 8 + g];
                const uint32_t vb1 = VTu[(vr0 + 4) * VSTR + nb2 * 8 + g];
                mma8(oacc[nb2][0], oacc[nb2][1], oacc[nb2][2], oacc[nb2][3],
                     pa0, pa1, pa2, pa3, vb0, vb1);
            }
        }
        __syncthreads();   // protect K/V/P smem before next tile load
    }

    // ---- finalize: row sums via butterfly within 4-lane groups ----
    #pragma unroll
    for (int off = 1; off <= 2; off <<= 1) {
        lsum0 += __shfl_xor_sync(0xffffffffu, lsum0, off);
        lsum1 += __shfl_xor_sync(0xffffffffu, lsum1, off);
    }
    const float inv0 = 1.0f / lsum0;
    const float inv1 = 1.0f / lsum1;
    if (q == 0) {
        g_inv[grow0] = inv0;
        g_inv[grow1] = inv1;
    }

    #pragma unroll
    for (int nb2 = 0; nb2 < 8; nb2++) {
        float2 o0; o0.x = oacc[nb2][0] * inv0; o0.y = oacc[nb2][1] * inv0;
        float2 o1; o1.x = oacc[nb2][2] * inv1; o1.y = oacc[nb2][3] * inv1;
        *(float2*)(Og + grow0 * DD + nb2 * 8 + 2 * q) = o0;
        *(float2*)(Og + grow1 * DD + nb2 * 8 + 2 * q) = o1;
    }
}

// ---- pass 2: normalize attn rows by 1/rowsum ----
__global__ void __launch_bounds__(256)
attn_norm(float* __restrict__ attn)
{
    const int row = blockIdx.x;
    const float inv = g_inv[row];
    float4* p = (float4*)(attn + (size_t)row * SK);
    const int i = threadIdx.x;
    #pragma unroll
    for (int k = 0; k < 2; k++) {
        float4 x = p[i + k * 256];
        x.x *= inv; x.y *= inv; x.z *= inv; x.w *= inv;
        p[i + k * 256] = x;
    }
}

extern "C" void kernel_launch(void* const* d_in, const int* in_sizes, int n_in,
                              void* d_out, int out_size)
{
    const float* Q    = (const float*)d_in[0];
    const float* K    = (const float*)d_in[1];
    const float* V    = (const float*)d_in[2];
    const int*   mask = (const int*)d_in[3];

    float* attn = (float*)d_out;                   // [B, SQ, SK]
    float* outp = attn + (size_t)BB * SQ * SK;     // [B, SQ, D]

    cudaFuncSetAttribute(attn_pass1,
                         cudaFuncAttributeMaxDynamicSharedMemorySize, SMEM_BYTES);

    dim3 grid(SQ / QB, BB);
    attn_pass1<<<grid, NT, SMEM_BYTES>>>(Q, K, V, mask, attn, outp);
    attn_norm<<<BB * SQ, 256>>>(attn);
}

// round 8
// speedup vs baseline: 1.2895x; 1.1892x over previous
#include <cuda_runtime.h>
#include <cstdint>
#include <cstddef>

#define BB 32
#define SQ 2048
#define SK 2048
#define DD 64
#define QB 128           // q rows per CTA
#define KB 128           // k cols per tile
#define NT 256
#define NTILES (SK/KB)

#define KSTR 68          // K tile row stride (floats)
#define VSTR 72          // V tile row stride
#define PSTR 132         // P tile row stride

// float-index offsets in dynamic smem
#define OFF_KHI 0                      // 128*KSTR = 8704
#define OFF_VT  (128*KSTR)             // 128*VSTR = 9216
#define OFF_P   (OFF_VT + 128*VSTR)    // 128*PSTR = 16896
#define SMEM_FLOATS (OFF_P + 128*PSTR) // 34816
#define SMEM_BYTES  (SMEM_FLOATS*4)    // 139264 B

__device__ float g_inv[BB * SQ];      // per-row 1/rowsum scratch

static __device__ __forceinline__ uint32_t f2tf(float x) {
    uint32_t r; asm("cvt.rna.tf32.f32 %0, %1;" : "=r"(r) : "f"(x)); return r;
}
static __device__ __forceinline__ void mma8(float& d0, float& d1, float& d2, float& d3,
                                            uint32_t a0, uint32_t a1, uint32_t a2, uint32_t a3,
                                            uint32_t b0, uint32_t b1) {
    asm volatile("mma.sync.aligned.m16n8k8.row.col.f32.tf32.tf32.f32 "
                 "{%0,%1,%2,%3}, {%4,%5,%6,%7}, {%8,%9}, {%0,%1,%2,%3};"
                 : "+f"(d0), "+f"(d1), "+f"(d2), "+f"(d3)
                 : "r"(a0), "r"(a1), "r"(a2), "r"(a3), "r"(b0), "r"(b1));
}

__global__ void __launch_bounds__(NT, 1)
attn_pass1(const float* __restrict__ Qg, const float* __restrict__ Kg,
           const float* __restrict__ Vg, const int* __restrict__ Mg,
           float* __restrict__ attn, float* __restrict__ Og)
{
    extern __shared__ float sm[];
    uint32_t* KHu = (uint32_t*)(sm + OFF_KHI);
    uint32_t* VTu = (uint32_t*)(sm + OFF_VT);
    uint32_t* Pu  = (uint32_t*)(sm + OFF_P);

    const int tid  = threadIdx.x;
    const int w    = tid >> 5;
    const int lane = tid & 31;
    const int q    = lane & 3;        // thread-in-group (col within fragment)
    const int g    = lane >> 2;       // group id (row within fragment)
    const int b    = blockIdx.y;
    const int qbase = blockIdx.x * QB;

    const int r0 = w * 16 + g;        // local q row (and r0+8)
    const size_t grow0 = (size_t)b * SQ + qbase + r0;
    const size_t grow1 = grow0 + 8;

    // ---- stage Q (scaled 0.125, hi/lo tf32 split) via KHI/VT regions, lift frags ----
    {
        uint32_t* QH = KHu;
        uint32_t* QL = VTu;
        const float4* Qv = (const float4*)(Qg + ((size_t)b * SQ + qbase) * DD);
        for (int v = tid; v < QB * DD / 4; v += NT) {
            int row = v >> 4, c = (v & 15) * 4;
            float4 x = Qv[v];
            x.x *= 0.125f; x.y *= 0.125f; x.z *= 0.125f; x.w *= 0.125f;
            uint4 hi, lo;
            hi.x = f2tf(x.x); lo.x = f2tf(x.x - __uint_as_float(hi.x));
            hi.y = f2tf(x.y); lo.y = f2tf(x.y - __uint_as_float(hi.y));
            hi.z = f2tf(x.z); lo.z = f2tf(x.z - __uint_as_float(hi.z));
            hi.w = f2tf(x.w); lo.w = f2tf(x.w - __uint_as_float(hi.w));
            *(uint4*)&QH[row * KSTR + c] = hi;
            *(uint4*)&QL[row * VSTR + c] = lo;
        }
    }
    __syncthreads();

    uint32_t qhi[8][4], qlo[8][4];
    #pragma unroll
    for (int s = 0; s < 8; s++) {
        const int c0 = s * 8 + q;
        qhi[s][0] = KHu[r0 * KSTR + c0];
        qhi[s][1] = KHu[(r0 + 8) * KSTR + c0];
        qhi[s][2] = KHu[r0 * KSTR + c0 + 4];
        qhi[s][3] = KHu[(r0 + 8) * KSTR + c0 + 4];
        qlo[s][0] = VTu[r0 * VSTR + c0];
        qlo[s][1] = VTu[(r0 + 8) * VSTR + c0];
        qlo[s][2] = VTu[r0 * VSTR + c0 + 4];
        qlo[s][3] = VTu[(r0 + 8) * VSTR + c0 + 4];
    }
    __syncthreads();

    float oacc[8][4];
    #pragma unroll
    for (int i = 0; i < 8; i++)
        oacc[i][0] = oacc[i][1] = oacc[i][2] = oacc[i][3] = 0.f;
    float lsum0 = 0.f, lsum1 = 0.f;

    for (int t = 0; t < NTILES; t++) {
        // ---- load K tile (tf32) + V tile (tf32) ----
        const float4* Kv = (const float4*)(Kg + ((size_t)b * SK + (size_t)t * KB) * DD);
        const float4* Vv = (const float4*)(Vg + ((size_t)b * SK + (size_t)t * KB) * DD);
        for (int v = tid; v < KB * DD / 4; v += NT) {
            int row = v >> 4, c = (v & 15) * 4;
            float4 x = Kv[v];
            uint4 kh;
            kh.x = f2tf(x.x); kh.y = f2tf(x.y); kh.z = f2tf(x.z); kh.w = f2tf(x.w);
            *(uint4*)&KHu[row * KSTR + c] = kh;
            float4 y = Vv[v];
            uint4 vt;
            vt.x = f2tf(y.x); vt.y = f2tf(y.y); vt.z = f2tf(y.z); vt.w = f2tf(y.w);
            *(uint4*)&VTu[row * VSTR + c] = vt;
        }
        __syncthreads();

        // ---- QK (2-term split: qhi*k + qlo*k) + fused epilogue ----
        #pragma unroll 1
        for (int nb = 0; nb < 16; nb++) {
            float a0 = 0.f, a1 = 0.f, a2 = 0.f, a3 = 0.f;     // qhi*k chain
            float c0 = 0.f, c1 = 0.f, c2 = 0.f, c3 = 0.f;     // qlo*k chain
            const int nrow = nb * 8 + g;
            #pragma unroll
            for (int s = 0; s < 8; s++) {
                const int cc = s * 8 + q;
                const uint32_t bh0 = KHu[nrow * KSTR + cc];
                const uint32_t bh1 = KHu[nrow * KSTR + cc + 4];
                mma8(a0, a1, a2, a3, qhi[s][0], qhi[s][1], qhi[s][2], qhi[s][3], bh0, bh1);
                mma8(c0, c1, c2, c3, qlo[s][0], qlo[s][1], qlo[s][2], qlo[s][3], bh0, bh1);
            }
            const float s00 = a0 + c0, s01 = a1 + c1, s10 = a2 + c2, s11 = a3 + c3;

            const int col = t * KB + nb * 8 + 2 * q;
            const int2 m0 = *(const int2*)(Mg + grow0 * SK + col);
            const int2 m1 = *(const int2*)(Mg + grow1 * SK + col);
            float e00 = m0.x ? __expf(s00) : 0.f;
            float e01 = m0.y ? __expf(s01) : 0.f;
            float e10 = m1.x ? __expf(s10) : 0.f;
            float e11 = m1.y ? __expf(s11) : 0.f;
            float2 w0; w0.x = e00; w0.y = e01;
            float2 w1; w1.x = e10; w1.y = e11;
            *(float2*)(attn + grow0 * SK + col) = w0;
            *(float2*)(attn + grow1 * SK + col) = w1;
            lsum0 += e00 + e01;
            lsum1 += e10 + e11;

            uint2 p0; p0.x = f2tf(e00); p0.y = f2tf(e01);
            uint2 p1; p1.x = f2tf(e10); p1.y = f2tf(e11);
            *(uint2*)&Pu[r0 * PSTR + nb * 8 + 2 * q] = p0;        // warp-private strip
            *(uint2*)&Pu[(r0 + 8) * PSTR + nb * 8 + 2 * q] = p1;
        }

        // ---- O += P @ V (k=128: 16 steps; n=64: 8 independent chains) ----
        #pragma unroll 1
        for (int s2 = 0; s2 < 16; s2++) {
            const int cc = s2 * 8 + q;
            const uint32_t pa0 = Pu[r0 * PSTR + cc];
            const uint32_t pa1 = Pu[(r0 + 8) * PSTR + cc];
            const uint32_t pa2 = Pu[r0 * PSTR + cc + 4];
            const uint32_t pa3 = Pu[(r0 + 8) * PSTR + cc + 4];
            const int vr0 = s2 * 8 + q;
            #pragma unroll
            for (int nb2 = 0; nb2 < 8; nb2++) {
                const uint32_t vb0 = VTu[vr0 * VSTR + nb2 * 8 + g];
                const uint32_t vb1 = VTu[(vr0 + 4) * VSTR + nb2 * 8 + g];
                mma8(oacc[nb2][0], oacc[nb2][1], oacc[nb2][2], oacc[nb2][3],
                     pa0, pa1, pa2, pa3, vb0, vb1);
            }
        }
        __syncthreads();   // protect K/V/P smem before next tile load
    }

    // ---- finalize: row sums via butterfly within 4-lane groups ----
    #pragma unroll
    for (int off = 1; off <= 2; off <<= 1) {
        lsum0 += __shfl_xor_sync(0xffffffffu, lsum0, off);
        lsum1 += __shfl_xor_sync(0xffffffffu, lsum1, off);
    }
    const float inv0 = 1.0f / lsum0;
    const float inv1 = 1.0f / lsum1;
    if (q == 0) {
        g_inv[grow0] = inv0;
        g_inv[grow1] = inv1;
    }

    #pragma unroll
    for (int nb2 = 0; nb2 < 8; nb2++) {
        float2 o0; o0.x = oacc[nb2][0] * inv0; o0.y = oacc[nb2][1] * inv0;
        float2 o1; o1.x = oacc[nb2][2] * inv1; o1.y = oacc[nb2][3] * inv1;
        *(float2*)(Og + grow0 * DD + nb2 * 8 + 2 * q) = o0;
        *(float2*)(Og + grow1 * DD + nb2 * 8 + 2 * q) = o1;
    }
}

// ---- pass 2: normalize attn rows by 1/rowsum ----
__global__ void __launch_bounds__(256)
attn_norm(float* __restrict__ attn)
{
    const int row = blockIdx.x;
    const float inv = g_inv[row];
    float4* p = (float4*)(attn + (size_t)row * SK);
    const int i = threadIdx.x;
    #pragma unroll
    for (int k = 0; k < 2; k++) {
        float4 x = p[i + k * 256];
        x.x *= inv; x.y *= inv; x.z *= inv; x.w *= inv;
        p[i + k * 256] = x;
    }
}

extern "C" void kernel_launch(void* const* d_in, const int* in_sizes, int n_in,
                              void* d_out, int out_size)
{
    const float* Q    = (const float*)d_in[0];
    const float* K    = (const float*)d_in[1];
    const float* V    = (const float*)d_in[2];
    const int*   mask = (const int*)d_in[3];

    float* attn = (float*)d_out;                   // [B, SQ, SK]
    float* outp = attn + (size_t)BB * SQ * SK;     // [B, SQ, D]

    cudaFuncSetAttribute(attn_pass1,
                         cudaFuncAttributeMaxDynamicSharedMemorySize, SMEM_BYTES);

    dim3 grid(SQ / QB, BB);
    attn_pass1<<<grid, NT, SMEM_BYTES>>>(Q, K, V, mask, attn, outp);
    attn_norm<<<BB * SQ, 256>>>(attn);
}